// round 14
// baseline (speedup 1.0000x reference)
#include <cuda_runtime.h>
#include <cuda_fp16.h>
#include <cstdint>
#include <math.h>

#define BSZ 8
#define SEQ 1024
#define DIM 1024
#define NH 16
#define DH 64
#define MTOK (BSZ*SEQ)        // 8192
#define FFD  (2*DIM)          // 2048
#define QKVD (3*DIM)          // 3072
#define NROW (BSZ*NH*SEQ)     // 131072
#define HSTR 72               // smem row stride in halves (conflict-free)
#define KSLAB 64

// ---------------- scratch (device globals; no runtime allocation) ----------
__device__ __half g_xh[MTOK*DIM];
__device__ __half g_wh[8*1024*1024];      // [Wq|Wk|Wv](3M), Wf(1M), W1(2M), W2(2M)
__device__ __half g_qkvh[MTOK*QKVD];
__device__ __half g_vth[BSZ*NH*DH*SEQ];   // V transposed per head: [z][d][s]
__device__ __half g_eh[(size_t)NROW*SEQ]; // unnormalized exp scores
__device__ __half g_attnh[MTOK*DIM];
__device__ __half g_h1h[MTOK*DIM];
__device__ __half g_ffnh[MTOK*FFD];
__device__ float  g_h1f[MTOK*DIM];
__device__ float  g_tmpf[MTOK*DIM];
__device__ float  g_bqkv[QKVD];
__device__ float  g_rowsum[NROW];
__device__ float  g_rowinv[NROW];

// ================= helpers =================================================
__device__ __forceinline__ uint32_t smem_u32(const void* p) {
    uint32_t a;
    asm("{ .reg .u64 t; cvta.to.shared.u64 t, %1; cvt.u32.u64 %0, t; }"
        : "=r"(a) : "l"(p));
    return a;
}
#define CP_ASYNC16(s, g) \
    asm volatile("cp.async.cg.shared.global [%0], [%1], 16;" :: "r"(s), "l"(g))
#define CP_COMMIT() asm volatile("cp.async.commit_group;")
#define CP_WAIT1()  asm volatile("cp.async.wait_group 1;")

__device__ __forceinline__ void mma_f16(float* d, const uint32_t* a, const uint32_t* b) {
    asm volatile(
        "mma.sync.aligned.m16n8k16.row.col.f32.f16.f16.f32 "
        "{%0,%1,%2,%3}, {%4,%5,%6,%7}, {%8,%9}, {%0,%1,%2,%3};"
        : "+f"(d[0]), "+f"(d[1]), "+f"(d[2]), "+f"(d[3])
        : "r"(a[0]), "r"(a[1]), "r"(a[2]), "r"(a[3]), "r"(b[0]), "r"(b[1]));
}

// ================= small utility kernels ===================================
struct RC7 {
    const float* in[7];
    __half* out[7];
    int n4[7];
};
__global__ __launch_bounds__(256) void round_h(RC7 rc)
{
    const int j = blockIdx.y;
    const float* __restrict__ in = rc.in[j];
    __half* __restrict__ out = rc.out[j];
    const int n4 = rc.n4[j];
    int i = blockIdx.x * blockDim.x + threadIdx.x;
    const int stride = gridDim.x * blockDim.x;
    for (; i < n4; i += stride) {
        float4 v = ((const float4*)in)[i];
        __half2 lo = __floats2half2_rn(v.x, v.y);
        __half2 hi = __floats2half2_rn(v.z, v.w);
        uint2 u;
        u.x = *(uint32_t*)&lo; u.y = *(uint32_t*)&hi;
        ((uint2*)out)[i] = u;
    }
}

__global__ __launch_bounds__(256) void zero_buf(float* __restrict__ p, int n)
{
    int i = blockIdx.x * blockDim.x + threadIdx.x;
    if (i < n) p[i] = 0.f;
}

__global__ __launch_bounds__(256) void recip_buf(
    const float* __restrict__ in, float* __restrict__ out, int n)
{
    int i = blockIdx.x * blockDim.x + threadIdx.x;
    if (i < n) out[i] = 1.0f / in[i];
}

__global__ __launch_bounds__(256) void concat_bias(
    const float* __restrict__ a, const float* __restrict__ b,
    const float* __restrict__ c, float* __restrict__ o)
{
    int i = blockIdx.x * blockDim.x + threadIdx.x;
    if (i < DIM) o[i] = a[i];
    else if (i < 2*DIM) o[i] = b[i - DIM];
    else if (i < 3*DIM) o[i] = c[i - 2*DIM];
}

// V transpose: qkv v-slice (s, d) -> vt[z][d][s]
__global__ __launch_bounds__(256) void transpose_v(
    const __half* __restrict__ qkv, __half* __restrict__ vt)
{
    __shared__ __half tile[32][33];
    const int z = blockIdx.z, b = z >> 4, h = z & 15;
    const int s0 = blockIdx.x * 32, d0 = blockIdx.y * 32;
    const int tx = threadIdx.x & 31, ty = threadIdx.x >> 5;  // 32 x 8
    const __half* src = qkv + (size_t)b * SEQ * QKVD + 2 * DIM + h * DH;
#pragma unroll
    for (int i = 0; i < 4; i++)
        tile[ty + 8 * i][tx] = src[(size_t)(s0 + ty + 8 * i) * QKVD + d0 + tx];
    __syncthreads();
    __half* dst = vt + (size_t)z * DH * SEQ;
#pragma unroll
    for (int i = 0; i < 4; i++)
        dst[(size_t)(d0 + ty + 8 * i) * SEQ + s0 + tx] = tile[tx][ty + 8 * i];
}

// ================= fp16 mma GEMM ===========================================
// MODE 0: plain NT gemm (A fp16 [M,K], B fp16 [N,K]); out: Ch fp16 and/or Cf
//         fp32; bias/scale(cols<scaleN)/res(fp32)/relu fused.
// MODE 1: per-head scores; epilogue writes e=exp(s) fp16 to Ch (col SEQ-1
//         masked 0) + atomic fp32 row sums.
// MODE 2: PV: A = e fp16, B = Vt fp16 (NT layout); A fragments normalized by
//         rowinv; fp32 P (=e*rinv) written to Cf from smem; attn fp16 to Ch.
// NT=256: warp tile 64x64, 1 CTA/SM; NT<=128: warp tile per WROWS, 2 CTA/SM.
template <int NT, int MODE>
__global__ __launch_bounds__(256, (NT == 256) ? 1 : 2) void gemm_h(
    const __half* __restrict__ A, const __half* __restrict__ B,
    const float* __restrict__ bias, const float* __restrict__ res,
    __half* __restrict__ Ch, float* __restrict__ Cf,
    int K, int lda, int ldb, int ldch, int ldcf,
    float scale, int scaleN, int relu,
    float* __restrict__ rowsum, const float* __restrict__ rowinv)
{
    constexpr int AFL = 128 * HSTR;          // halves per A buffer
    constexpr int BFL = NT * HSTR;

    constexpr int WROWS = (NT >= 128) ? 2 : 4;
    constexpr int WM = 128 / WROWS;
    constexpr int WN = NT / (8 / WROWS);
    constexpr int MT  = WM / 16;
    constexpr int NTg = WN / 8;

    extern __shared__ char dynsmem[];
    __half* const AsB = (__half*)dynsmem;
    __half* const BsB = AsB + 2 * AFL;

    const int tid = threadIdx.x;
    const int wid = tid >> 5, lane = tid & 31;
    const int g = lane >> 2, t = lane & 3;
    const int wm = (wid % WROWS) * WM;
    const int wn = (wid / WROWS) * WN;

    const int n0 = blockIdx.x * NT;
    const int m0 = blockIdx.y * 128;
    const __half* Ap; const __half* Bp;
    __half* Chp = Ch; float* Cfp = Cf;
    if (MODE == 0) { Ap = A; Bp = B; }
    else if (MODE == 1) {
        const int z = blockIdx.z, b = z >> 4, h = z & 15;
        Ap = A + (size_t)b * SEQ * lda + h * DH;
        Bp = B + (size_t)b * SEQ * ldb + h * DH;
        Chp = Ch + (size_t)z * SEQ * SEQ;
    } else {
        const int z = blockIdx.z, b = z >> 4, h = z & 15;
        Ap = A + (size_t)z * SEQ * SEQ;           // e rows for this (b,h)
        Bp = B + (size_t)z * DH * SEQ;            // Vt rows
        Chp = Ch + (size_t)b * SEQ * ldch + h * DH;
        Cfp = Cf + (size_t)z * SEQ * SEQ;
    }

    // MODE 2: per-thread fixed row-normalizers
    __half2 rv2[MT][2];
    float rvw[4];
    if (MODE == 2) {
        const float* rinv = rowinv + (size_t)blockIdx.z * SEQ + m0;
#pragma unroll
        for (int mt = 0; mt < MT; mt++) {
            float lo = rinv[wm + mt * 16 + g];
            float hi = rinv[wm + mt * 16 + g + 8];
            rv2[mt][0] = __float2half2_rn(lo);
            rv2[mt][1] = __float2half2_rn(hi);
        }
#pragma unroll
        for (int i = 0; i < 4; i++)
            rvw[i] = rinv[(i * 256 + tid) >> 3];
    }

    float acc[MT][NTg][4];
#pragma unroll
    for (int i = 0; i < MT; i++)
#pragma unroll
        for (int j = 0; j < NTg; j++)
#pragma unroll
            for (int q = 0; q < 4; q++) acc[i][j][q] = 0.f;

    const int Kc = K / KSLAB;

    auto load_slab = [&](int c, int buf) {
        const int kt = c * KSLAB;
        __half* As = AsB + buf * AFL;
        __half* Bs = BsB + buf * BFL;
        // A: 128 rows x 8 chunks (16B = 8 halves)
#pragma unroll
        for (int i = 0; i < 4; i++) {
            const int lin = i * 256 + tid;
            const int row = lin >> 3, c16 = lin & 7;
            CP_ASYNC16(smem_u32(As + row * HSTR + c16 * 8),
                       Ap + (size_t)(m0 + row) * lda + kt + c16 * 8);
        }
        // B: NT rows x 8 chunks
#pragma unroll
        for (int i = 0; i < NT / 32; i++) {
            const int lin = i * 256 + tid;
            const int row = lin >> 3, c16 = lin & 7;
            CP_ASYNC16(smem_u32(Bs + row * HSTR + c16 * 8),
                       Bp + (size_t)(n0 + row) * ldb + kt + c16 * 8);
        }
    };

    load_slab(0, 0);
    CP_COMMIT();

    for (int c = 0; c < Kc; c++) {
        if (c + 1 < Kc) load_slab(c + 1, (c + 1) & 1);
        CP_COMMIT();
        CP_WAIT1();
        __syncthreads();

        const __half* As = AsB + (c & 1) * AFL;
        const __half* Bs = BsB + (c & 1) * BFL;
#pragma unroll
        for (int ks = 0; ks < KSLAB / 16; ks++) {
            const int kk = ks * 16;
            uint32_t af[MT][4];
#pragma unroll
            for (int mt = 0; mt < MT; mt++) {
                const __half* ar = As + (wm + mt * 16 + g) * HSTR + kk + 2 * t;
                af[mt][0] = *(const uint32_t*)(ar);
                af[mt][1] = *(const uint32_t*)(ar + 8 * HSTR);
                af[mt][2] = *(const uint32_t*)(ar + 8);
                af[mt][3] = *(const uint32_t*)(ar + 8 * HSTR + 8);
                if (MODE == 2) {
#pragma unroll
                    for (int q = 0; q < 4; q++) {
                        __half2 v = __hmul2(*(__half2*)&af[mt][q], rv2[mt][q & 1]);
                        af[mt][q] = *(uint32_t*)&v;
                    }
                }
            }
            uint32_t bf[NTg][2];
#pragma unroll
            for (int nt = 0; nt < NTg; nt++) {
                const __half* br = Bs + (wn + nt * 8 + g) * HSTR + kk + 2 * t;
                bf[nt][0] = *(const uint32_t*)(br);
                bf[nt][1] = *(const uint32_t*)(br + 8);
            }
#pragma unroll
            for (int mt = 0; mt < MT; mt++)
#pragma unroll
                for (int nt = 0; nt < NTg; nt++)
                    mma_f16(acc[mt][nt], af[mt], bf[nt]);
        }

        if (MODE == 2) {
            // fp32 P = e * rinv written from the smem slab
            const int kt = c * KSLAB;
#pragma unroll
            for (int i = 0; i < 4; i++) {
                const int lin = i * 256 + tid;
                const int row = lin >> 3, c16 = lin & 7;
                const __half* sp = As + row * HSTR + c16 * 8;
                uint2 r0 = *(const uint2*)sp;
                uint2 r1 = *(const uint2*)(sp + 4);
                const float iv = rvw[i];
                float2 f0 = __half22float2(*(__half2*)&r0.x);
                float2 f1 = __half22float2(*(__half2*)&r0.y);
                float2 f2 = __half22float2(*(__half2*)&r1.x);
                float2 f3 = __half22float2(*(__half2*)&r1.y);
                float* dp = Cfp + (size_t)(m0 + row) * ldcf + kt + c16 * 8;
                *(float4*)dp = make_float4(f0.x*iv, f0.y*iv, f1.x*iv, f1.y*iv);
                *(float4*)(dp + 4) = make_float4(f2.x*iv, f2.y*iv, f3.x*iv, f3.y*iv);
            }
        }
        __syncthreads();
    }

    // ---- epilogue ----
    if (MODE == 1) {
        float rpart[MT][2];
#pragma unroll
        for (int mt = 0; mt < MT; mt++) { rpart[mt][0] = 0.f; rpart[mt][1] = 0.f; }
#pragma unroll
        for (int mt = 0; mt < MT; mt++) {
            const int row = m0 + wm + mt * 16 + g;
#pragma unroll
            for (int nt = 0; nt < NTg; nt++) {
                const int col = n0 + wn + nt * 8 + 2 * t;
                float e0 = __expf(acc[mt][nt][0]);
                float e1 = __expf(acc[mt][nt][1]);
                float e2 = __expf(acc[mt][nt][2]);
                float e3 = __expf(acc[mt][nt][3]);
                if (col == SEQ - 1)     { e0 = 0.f; e2 = 0.f; }
                if (col + 1 == SEQ - 1) { e1 = 0.f; e3 = 0.f; }
                *(__half2*)&Chp[(size_t)row * ldch + col] = __floats2half2_rn(e0, e1);
                *(__half2*)&Chp[(size_t)(row + 8) * ldch + col] = __floats2half2_rn(e2, e3);
                rpart[mt][0] += e0 + e1;
                rpart[mt][1] += e2 + e3;
            }
        }
#pragma unroll
        for (int mt = 0; mt < MT; mt++) {
#pragma unroll
            for (int s = 0; s < 2; s++) {
                rpart[mt][s] += __shfl_xor_sync(0xffffffffu, rpart[mt][s], 1);
                rpart[mt][s] += __shfl_xor_sync(0xffffffffu, rpart[mt][s], 2);
            }
        }
        if (t == 0) {
            float* rs = rowsum + (size_t)blockIdx.z * SEQ + m0;
#pragma unroll
            for (int mt = 0; mt < MT; mt++) {
                atomicAdd(&rs[wm + mt * 16 + g],     rpart[mt][0]);
                atomicAdd(&rs[wm + mt * 16 + g + 8], rpart[mt][1]);
            }
        }
        return;
    }

#pragma unroll
    for (int mt = 0; mt < MT; mt++) {
        const int row = m0 + wm + mt * 16 + g;
#pragma unroll
        for (int nt = 0; nt < NTg; nt++) {
            const int col = n0 + wn + nt * 8 + 2 * t;
            float o0 = acc[mt][nt][0], o1 = acc[mt][nt][1];
            float o2 = acc[mt][nt][2], o3 = acc[mt][nt][3];
            if (bias) {
                const float b0 = bias[col], b1 = bias[col + 1];
                o0 += b0; o1 += b1; o2 += b0; o3 += b1;
            }
            if (scale != 1.f && col < scaleN) {
                o0 *= scale; o1 *= scale; o2 *= scale; o3 *= scale;
            }
            if (res) {
                float2 r0 = *(const float2*)&res[(size_t)row * ldcf + col];
                float2 r1 = *(const float2*)&res[(size_t)(row + 8) * ldcf + col];
                o0 += r0.x; o1 += r0.y; o2 += r1.x; o3 += r1.y;
            }
            if (relu) {
                o0 = fmaxf(o0, 0.f); o1 = fmaxf(o1, 0.f);
                o2 = fmaxf(o2, 0.f); o3 = fmaxf(o3, 0.f);
            }
            if (Ch) {
                *(__half2*)&Chp[(size_t)row * ldch + col] = __floats2half2_rn(o0, o1);
                *(__half2*)&Chp[(size_t)(row + 8) * ldch + col] = __floats2half2_rn(o2, o3);
            }
            if (Cf && MODE == 0) {
                *(float2*)&Cfp[(size_t)row * ldcf + col]       = make_float2(o0, o1);
                *(float2*)&Cfp[(size_t)(row + 8) * ldcf + col] = make_float2(o2, o3);
            }
        }
    }
}

// ================= layernorm (fp32 in; fp32 and/or fp16 out) ===============
__global__ __launch_bounds__(256) void layernorm_row(
    const float* __restrict__ in, float* __restrict__ outf,
    __half* __restrict__ outh,
    const float* __restrict__ g, const float* __restrict__ be)
{
    __shared__ float sm[8], sq[8];
    const size_t base = (size_t)blockIdx.x * DIM;
    const int tid = threadIdx.x;
    const int lane = tid & 31, wid = tid >> 5;

    float4 v = *(const float4*)&in[base + tid*4];
    float s  = v.x + v.y + v.z + v.w;
    float s2 = v.x*v.x + v.y*v.y + v.z*v.z + v.w*v.w;
#pragma unroll
    for (int o = 16; o; o >>= 1) {
        s  += __shfl_xor_sync(0xffffffffu, s,  o);
        s2 += __shfl_xor_sync(0xffffffffu, s2, o);
    }
    if (lane == 0) { sm[wid] = s; sq[wid] = s2; }
    __syncthreads();
    if (tid == 0) {
        float tt = 0.f, t2 = 0.f;
#pragma unroll
        for (int i = 0; i < 8; i++) { tt += sm[i]; t2 += sq[i]; }
        sm[0] = tt; sq[0] = t2;
    }
    __syncthreads();
    const float mean = sm[0] * (1.f / DIM);
    const float var  = sq[0] * (1.f / DIM) - mean * mean;
    const float r = rsqrtf(var + 1e-5f);

    float4 gg = *(const float4*)&g[tid*4];
    float4 bb = *(const float4*)&be[tid*4];
    float4 o4;
    o4.x = (v.x - mean) * r * gg.x + bb.x;
    o4.y = (v.y - mean) * r * gg.y + bb.y;
    o4.z = (v.z - mean) * r * gg.z + bb.z;
    o4.w = (v.w - mean) * r * gg.w + bb.w;
    if (outf) *(float4*)&outf[base + tid*4] = o4;
    if (outh) {
        __half2 lo = __floats2half2_rn(o4.x, o4.y);
        __half2 hi = __floats2half2_rn(o4.z, o4.w);
        uint2 u; u.x = *(uint32_t*)&lo; u.y = *(uint32_t*)&hi;
        *(uint2*)&outh[base + tid*4] = u;
    }
}

// ================= launcher ================================================
static const int SMEM_G256 = 2 * (128 + 256) * HSTR * 2;   // 110592
static const int SMEM_PV   = 2 * (128 + 64) * HSTR * 2;    // 55296

extern "C" void kernel_launch(void* const* d_in, const int* in_sizes, int n_in,
                              void* d_out, int out_size)
{
    const float* x  = (const float*)d_in[0];
    const float* Wq = (const float*)d_in[1];
    const float* bq = (const float*)d_in[2];
    const float* Wk = (const float*)d_in[3];
    const float* bk = (const float*)d_in[4];
    const float* Wv = (const float*)d_in[5];
    const float* bv = (const float*)d_in[6];
    const float* Wf = (const float*)d_in[7];
    const float* bf = (const float*)d_in[8];
    const float* W1 = (const float*)d_in[9];
    const float* b1 = (const float*)d_in[10];
    const float* W2 = (const float*)d_in[11];
    const float* b2 = (const float*)d_in[12];
    const float* g1 = (const float*)d_in[13];
    const float* be1= (const float*)d_in[14];
    const float* g2 = (const float*)d_in[15];
    const float* be2= (const float*)d_in[16];

    float* out   = (float*)d_out;
    float* score = out + (size_t)MTOK * DIM;

    __half *pxh, *pwh, *pqkvh, *pvth, *peh, *pattnh, *ph1h, *pffnh;
    float *ph1f, *ptmpf, *pbias, *prsum, *prinv;
    cudaGetSymbolAddress((void**)&pxh,   g_xh);
    cudaGetSymbolAddress((void**)&pwh,   g_wh);
    cudaGetSymbolAddress((void**)&pqkvh, g_qkvh);
    cudaGetSymbolAddress((void**)&pvth,  g_vth);
    cudaGetSymbolAddress((void**)&peh,   g_eh);
    cudaGetSymbolAddress((void**)&pattnh,g_attnh);
    cudaGetSymbolAddress((void**)&ph1h,  g_h1h);
    cudaGetSymbolAddress((void**)&pffnh, g_ffnh);
    cudaGetSymbolAddress((void**)&ph1f,  g_h1f);
    cudaGetSymbolAddress((void**)&ptmpf, g_tmpf);
    cudaGetSymbolAddress((void**)&pbias, g_bqkv);
    cudaGetSymbolAddress((void**)&prsum, g_rowsum);
    cudaGetSymbolAddress((void**)&prinv, g_rowinv);

    __half* hWqkv = pwh;                    // 3M halves
    __half* hWf   = pwh + 3*1024*1024;
    __half* hW1   = pwh + 4*1024*1024;
    __half* hW2   = pwh + 6*1024*1024;

    cudaFuncSetAttribute(gemm_h<256,0>, cudaFuncAttributeMaxDynamicSharedMemorySize, SMEM_G256);
    cudaFuncSetAttribute(gemm_h<256,1>, cudaFuncAttributeMaxDynamicSharedMemorySize, SMEM_G256);
    cudaFuncSetAttribute(gemm_h<64,2>,  cudaFuncAttributeMaxDynamicSharedMemorySize, SMEM_PV);

    const float isq = 0.125f;  // 1/sqrt(64)

    // ---- prep: convert operands to fp16, bias concat, rowsum zero ----
    RC7 rc;
    rc.in[0] = x;  rc.out[0] = pxh;                 rc.n4[0] = MTOK*DIM/4;
    rc.in[1] = Wq; rc.out[1] = hWqkv;               rc.n4[1] = DIM*DIM/4;
    rc.in[2] = Wk; rc.out[2] = hWqkv + 1024*1024;   rc.n4[2] = DIM*DIM/4;
    rc.in[3] = Wv; rc.out[3] = hWqkv + 2*1024*1024; rc.n4[3] = DIM*DIM/4;
    rc.in[4] = Wf; rc.out[4] = hWf;                 rc.n4[4] = DIM*DIM/4;
    rc.in[5] = W1; rc.out[5] = hW1;                 rc.n4[5] = FFD*DIM/4;
    rc.in[6] = W2; rc.out[6] = hW2;                 rc.n4[6] = FFD*DIM/4;
    round_h<<<dim3(512, 7), 256>>>(rc);
    concat_bias<<<12, 256>>>(bq, bk, bv, pbias);
    zero_buf<<<NROW/256, 256>>>(prsum, NROW);

    // ---- fused QKV projection -> fp16 qkv ----
    gemm_h<256,0><<<dim3(QKVD/256, MTOK/128), 256, SMEM_G256>>>(
        pxh, hWqkv, pbias, nullptr, pqkvh, nullptr,
        DIM, DIM, DIM, QKVD, QKVD, isq, DIM, 0, nullptr, nullptr);

    // ---- V transpose for PV ----
    transpose_v<<<dim3(SEQ/32, DH/32, BSZ*NH), 256>>>(pqkvh, pvth);

    // ---- scores: e = exp(q.k^T) fp16 -> g_eh; rowsums accumulated ----
    gemm_h<256,1><<<dim3(SEQ/256, SEQ/128, BSZ*NH), 256, SMEM_G256>>>(
        pqkvh, pqkvh + DIM, nullptr, nullptr, peh, nullptr,
        DH, QKVD, QKVD, SEQ, SEQ, 1.f, 0, 0, prsum, nullptr);
    recip_buf<<<NROW/256, 256>>>(prsum, prinv, NROW);

    // ---- PV: attn fp16; fp32 P -> d_out score region ----
    gemm_h<64,2><<<dim3(1, SEQ/128, BSZ*NH), 256, SMEM_PV>>>(
        peh, pvth, nullptr, nullptr, pattnh, score,
        SEQ, SEQ, SEQ, DIM, SEQ, 1.f, 0, 0, nullptr, prinv);

    // ---- output projection + residual (x fp32), LN1 ----
    gemm_h<256,0><<<dim3(DIM/256, MTOK/128), 256, SMEM_G256>>>(
        pattnh, hWf, bf, x, nullptr, ph1f,
        DIM, DIM, DIM, DIM, DIM, 1.f, 0, 0, nullptr, nullptr);
    layernorm_row<<<MTOK, 256>>>(ph1f, ph1f, ph1h, g1, be1);

    // ---- FFN ----
    gemm_h<256,0><<<dim3(FFD/256, MTOK/128), 256, SMEM_G256>>>(
        ph1h, hW1, b1, nullptr, pffnh, nullptr,
        DIM, DIM, DIM, FFD, FFD, 1.f, 0, 1, nullptr, nullptr);
    gemm_h<256,0><<<dim3(DIM/256, MTOK/128), 256, SMEM_G256>>>(
        pffnh, hW2, b2, ph1f, nullptr, ptmpf,
        FFD, FFD, FFD, DIM, DIM, 1.f, 0, 0, nullptr, nullptr);
    layernorm_row<<<MTOK, 256>>>(ptmpf, out, nullptr, g2, be2);
}

// round 16
// speedup vs baseline: 1.6135x; 1.6135x over previous
#include <cuda_runtime.h>
#include <cuda_fp16.h>
#include <cstdint>
#include <math.h>

#define BSZ 8
#define SEQ 1024
#define DIM 1024
#define NH 16
#define DH 64
#define MTOK (BSZ*SEQ)        // 8192
#define FFD  (2*DIM)          // 2048
#define QKVD (3*DIM)          // 3072
#define NROW (BSZ*NH*SEQ)     // 131072
#define HSTR 72               // smem row stride in halves (conflict-free)
#define KSLAB 64

// ---------------- scratch (device globals; no runtime allocation) ----------
__device__ __half g_xh[MTOK*DIM];
__device__ __half g_wh[8*1024*1024];      // [Wq|Wk|Wv](3M), Wf(1M), W1(2M), W2(2M)
__device__ __half g_qkvh[MTOK*QKVD];
__device__ __half g_vth[BSZ*NH*DH*SEQ];   // V transposed per head: [z][d][s]
__device__ __half g_eh[(size_t)NROW*SEQ]; // unnormalized exp scores
__device__ __half g_attnh[MTOK*DIM];
__device__ __half g_h1h[MTOK*DIM];
__device__ __half g_ffnh[MTOK*FFD];
__device__ float  g_h1f[MTOK*DIM];
__device__ float  g_tmpf[MTOK*DIM];
__device__ float  g_bqkv[QKVD];
__device__ float  g_rowsum[NROW];
__device__ float  g_rowinv[NROW];

// ================= helpers =================================================
__device__ __forceinline__ uint32_t smem_u32(const void* p) {
    uint32_t a;
    asm("{ .reg .u64 t; cvta.to.shared.u64 t, %1; cvt.u32.u64 %0, t; }"
        : "=r"(a) : "l"(p));
    return a;
}
#define CP_ASYNC16(s, g) \
    asm volatile("cp.async.cg.shared.global [%0], [%1], 16;" :: "r"(s), "l"(g))
#define CP_COMMIT() asm volatile("cp.async.commit_group;")
#define CP_WAIT0()  asm volatile("cp.async.wait_group 0;")

__device__ __forceinline__ void mma_f16(float* d, const uint32_t* a, const uint32_t* b) {
    asm volatile(
        "mma.sync.aligned.m16n8k16.row.col.f32.f16.f16.f32 "
        "{%0,%1,%2,%3}, {%4,%5,%6,%7}, {%8,%9}, {%0,%1,%2,%3};"
        : "+f"(d[0]), "+f"(d[1]), "+f"(d[2]), "+f"(d[3])
        : "r"(a[0]), "r"(a[1]), "r"(a[2]), "r"(a[3]), "r"(b[0]), "r"(b[1]));
}

// ================= small utility kernels ===================================
struct RC7 {
    const float* in[7];
    __half* out[7];
    int n4[7];
};
__global__ __launch_bounds__(256) void round_h(RC7 rc)
{
    const int j = blockIdx.y;
    const float* __restrict__ in = rc.in[j];
    __half* __restrict__ out = rc.out[j];
    const int n4 = rc.n4[j];
    int i = blockIdx.x * blockDim.x + threadIdx.x;
    const int stride = gridDim.x * blockDim.x;
    for (; i < n4; i += stride) {
        float4 v = ((const float4*)in)[i];
        __half2 lo = __floats2half2_rn(v.x, v.y);
        __half2 hi = __floats2half2_rn(v.z, v.w);
        uint2 u;
        u.x = *(uint32_t*)&lo; u.y = *(uint32_t*)&hi;
        ((uint2*)out)[i] = u;
    }
}

__global__ __launch_bounds__(256) void zero_buf(float* __restrict__ p, int n)
{
    int i = blockIdx.x * blockDim.x + threadIdx.x;
    if (i < n) p[i] = 0.f;
}

__global__ __launch_bounds__(256) void recip_buf(
    const float* __restrict__ in, float* __restrict__ out, int n)
{
    int i = blockIdx.x * blockDim.x + threadIdx.x;
    if (i < n) out[i] = 1.0f / in[i];
}

__global__ __launch_bounds__(256) void concat_bias(
    const float* __restrict__ a, const float* __restrict__ b,
    const float* __restrict__ c, float* __restrict__ o)
{
    int i = blockIdx.x * blockDim.x + threadIdx.x;
    if (i < DIM) o[i] = a[i];
    else if (i < 2*DIM) o[i] = b[i - DIM];
    else if (i < 3*DIM) o[i] = c[i - 2*DIM];
}

// V transpose: qkv v-slice (s, d) -> vt[z][d][s]
__global__ __launch_bounds__(256) void transpose_v(
    const __half* __restrict__ qkv, __half* __restrict__ vt)
{
    __shared__ __half tile[32][33];
    const int z = blockIdx.z, b = z >> 4, h = z & 15;
    const int s0 = blockIdx.x * 32, d0 = blockIdx.y * 32;
    const int tx = threadIdx.x & 31, ty = threadIdx.x >> 5;  // 32 x 8
    const __half* src = qkv + (size_t)b * SEQ * QKVD + 2 * DIM + h * DH;
#pragma unroll
    for (int i = 0; i < 4; i++)
        tile[ty + 8 * i][tx] = src[(size_t)(s0 + ty + 8 * i) * QKVD + d0 + tx];
    __syncthreads();
    __half* dst = vt + (size_t)z * DH * SEQ;
#pragma unroll
    for (int i = 0; i < 4; i++)
        dst[(size_t)(d0 + ty + 8 * i) * SEQ + s0 + tx] = tile[tx][ty + 8 * i];
}

// ================= fp16 mma GEMM ===========================================
// Single __syncthreads per K-slab: WAIT0 -> sync -> issue next loads -> MMA.
// Invariant: exactly one cp.async group outstanding at the wait point, so
// wait_group 0 completes the current slab; next-slab loads overlap compute.
// MODE 0: plain NT gemm (A fp16 [M,K], B fp16 [N,K]); out: Ch fp16 and/or Cf
//         fp32; bias/scale(cols<scaleN)/res(fp32)/relu fused.
// MODE 1: per-head scores; epilogue writes e=exp(s) fp16 to Ch (col SEQ-1
//         masked 0) + atomic fp32 row sums.
// MODE 2: PV: A = e fp16, B = Vt fp16 (NT layout); A fragments normalized by
//         rowinv; fp32 P (=e*rinv) written to Cf from smem; attn fp16 to Ch.
template <int NT, int MODE>
__global__ __launch_bounds__(256, 2) void gemm_h(
    const __half* __restrict__ A, const __half* __restrict__ B,
    const float* __restrict__ bias, const float* __restrict__ res,
    __half* __restrict__ Ch, float* __restrict__ Cf,
    int K, int lda, int ldb, int ldch, int ldcf,
    float scale, int scaleN, int relu,
    float* __restrict__ rowsum, const float* __restrict__ rowinv)
{
    constexpr int AFL = 128 * HSTR;          // halves per A buffer
    constexpr int BFL = NT * HSTR;

    constexpr int WROWS = (NT == 128) ? 2 : 4;
    constexpr int WM = 128 / WROWS;
    constexpr int WN = NT / (8 / WROWS);
    constexpr int MT  = WM / 16;
    constexpr int NTg = WN / 8;

    extern __shared__ char dynsmem[];
    __half* const AsB = (__half*)dynsmem;
    __half* const BsB = AsB + 2 * AFL;

    const int tid = threadIdx.x;
    const int wid = tid >> 5, lane = tid & 31;
    const int g = lane >> 2, t = lane & 3;
    const int wm = (wid % WROWS) * WM;
    const int wn = (wid / WROWS) * WN;

    const int n0 = blockIdx.x * NT;
    const int m0 = blockIdx.y * 128;
    const __half* Ap; const __half* Bp;
    __half* Chp = Ch; float* Cfp = Cf;
    if (MODE == 0) { Ap = A; Bp = B; }
    else if (MODE == 1) {
        const int z = blockIdx.z, b = z >> 4, h = z & 15;
        Ap = A + (size_t)b * SEQ * lda + h * DH;
        Bp = B + (size_t)b * SEQ * ldb + h * DH;
        Chp = Ch + (size_t)z * SEQ * SEQ;
    } else {
        const int z = blockIdx.z, b = z >> 4, h = z & 15;
        Ap = A + (size_t)z * SEQ * SEQ;           // e rows for this (b,h)
        Bp = B + (size_t)z * DH * SEQ;            // Vt rows
        Chp = Ch + (size_t)b * SEQ * ldch + h * DH;
        Cfp = Cf + (size_t)z * SEQ * SEQ;
    }

    // MODE 2: per-thread fixed row-normalizers
    __half2 rv2[MT][2];
    float rvw[4];
    if (MODE == 2) {
        const float* rinv = rowinv + (size_t)blockIdx.z * SEQ + m0;
#pragma unroll
        for (int mt = 0; mt < MT; mt++) {
            float lo = rinv[wm + mt * 16 + g];
            float hi = rinv[wm + mt * 16 + g + 8];
            rv2[mt][0] = __float2half2_rn(lo);
            rv2[mt][1] = __float2half2_rn(hi);
        }
#pragma unroll
        for (int i = 0; i < 4; i++)
            rvw[i] = rinv[(i * 256 + tid) >> 3];
    }

    float acc[MT][NTg][4];
#pragma unroll
    for (int i = 0; i < MT; i++)
#pragma unroll
        for (int j = 0; j < NTg; j++)
#pragma unroll
            for (int q = 0; q < 4; q++) acc[i][j][q] = 0.f;

    const int Kc = K / KSLAB;

    auto load_slab = [&](int c, int buf) {
        const int kt = c * KSLAB;
        __half* As = AsB + buf * AFL;
        __half* Bs = BsB + buf * BFL;
        // A: 128 rows x 8 chunks (16B = 8 halves)
#pragma unroll
        for (int i = 0; i < 4; i++) {
            const int lin = i * 256 + tid;
            const int row = lin >> 3, c16 = lin & 7;
            CP_ASYNC16(smem_u32(As + row * HSTR + c16 * 8),
                       Ap + (size_t)(m0 + row) * lda + kt + c16 * 8);
        }
        // B: NT rows x 8 chunks
#pragma unroll
        for (int i = 0; i < NT / 32; i++) {
            const int lin = i * 256 + tid;
            const int row = lin >> 3, c16 = lin & 7;
            CP_ASYNC16(smem_u32(Bs + row * HSTR + c16 * 8),
                       Bp + (size_t)(n0 + row) * ldb + kt + c16 * 8);
        }
    };

    load_slab(0, 0);
    CP_COMMIT();

    for (int c = 0; c < Kc; c++) {
        CP_WAIT0();          // complete slab c (the only outstanding group)
        __syncthreads();
        // issue next slab AFTER the sync: its target buffer was last read in
        // iteration c-1, which the sync proves complete on all warps.
        if (c + 1 < Kc) {
            load_slab(c + 1, (c + 1) & 1);
            CP_COMMIT();
        }

        const __half* As = AsB + (c & 1) * AFL;
        const __half* Bs = BsB + (c & 1) * BFL;
#pragma unroll
        for (int ks = 0; ks < KSLAB / 16; ks++) {
            const int kk = ks * 16;
            uint32_t af[MT][4];
#pragma unroll
            for (int mt = 0; mt < MT; mt++) {
                const __half* ar = As + (wm + mt * 16 + g) * HSTR + kk + 2 * t;
                af[mt][0] = *(const uint32_t*)(ar);
                af[mt][1] = *(const uint32_t*)(ar + 8 * HSTR);
                af[mt][2] = *(const uint32_t*)(ar + 8);
                af[mt][3] = *(const uint32_t*)(ar + 8 * HSTR + 8);
                if (MODE == 2) {
#pragma unroll
                    for (int q = 0; q < 4; q++) {
                        __half2 v = __hmul2(*(__half2*)&af[mt][q], rv2[mt][q & 1]);
                        af[mt][q] = *(uint32_t*)&v;
                    }
                }
            }
            uint32_t bf[NTg][2];
#pragma unroll
            for (int nt = 0; nt < NTg; nt++) {
                const __half* br = Bs + (wn + nt * 8 + g) * HSTR + kk + 2 * t;
                bf[nt][0] = *(const uint32_t*)(br);
                bf[nt][1] = *(const uint32_t*)(br + 8);
            }
#pragma unroll
            for (int mt = 0; mt < MT; mt++)
#pragma unroll
                for (int nt = 0; nt < NTg; nt++)
                    mma_f16(acc[mt][nt], af[mt], bf[nt]);
        }

        if (MODE == 2) {
            // fp32 P = e * rinv written from the smem slab
            const int kt = c * KSLAB;
#pragma unroll
            for (int i = 0; i < 4; i++) {
                const int lin = i * 256 + tid;
                const int row = lin >> 3, c16 = lin & 7;
                const __half* sp = As + row * HSTR + c16 * 8;
                uint2 r0 = *(const uint2*)sp;
                uint2 r1 = *(const uint2*)(sp + 4);
                const float iv = rvw[i];
                float2 f0 = __half22float2(*(__half2*)&r0.x);
                float2 f1 = __half22float2(*(__half2*)&r0.y);
                float2 f2 = __half22float2(*(__half2*)&r1.x);
                float2 f3 = __half22float2(*(__half2*)&r1.y);
                float* dp = Cfp + (size_t)(m0 + row) * ldcf + kt + c16 * 8;
                *(float4*)dp = make_float4(f0.x*iv, f0.y*iv, f1.x*iv, f1.y*iv);
                *(float4*)(dp + 4) = make_float4(f2.x*iv, f2.y*iv, f3.x*iv, f3.y*iv);
            }
        }
    }

    // ---- epilogue ----
    if (MODE == 1) {
        float rpart[MT][2];
#pragma unroll
        for (int mt = 0; mt < MT; mt++) { rpart[mt][0] = 0.f; rpart[mt][1] = 0.f; }
#pragma unroll
        for (int mt = 0; mt < MT; mt++) {
            const int row = m0 + wm + mt * 16 + g;
#pragma unroll
            for (int nt = 0; nt < NTg; nt++) {
                const int col = n0 + wn + nt * 8 + 2 * t;
                float e0 = __expf(acc[mt][nt][0]);
                float e1 = __expf(acc[mt][nt][1]);
                float e2 = __expf(acc[mt][nt][2]);
                float e3 = __expf(acc[mt][nt][3]);
                if (col == SEQ - 1)     { e0 = 0.f; e2 = 0.f; }
                if (col + 1 == SEQ - 1) { e1 = 0.f; e3 = 0.f; }
                *(__half2*)&Chp[(size_t)row * ldch + col] = __floats2half2_rn(e0, e1);
                *(__half2*)&Chp[(size_t)(row + 8) * ldch + col] = __floats2half2_rn(e2, e3);
                rpart[mt][0] += e0 + e1;
                rpart[mt][1] += e2 + e3;
            }
        }
#pragma unroll
        for (int mt = 0; mt < MT; mt++) {
#pragma unroll
            for (int s = 0; s < 2; s++) {
                rpart[mt][s] += __shfl_xor_sync(0xffffffffu, rpart[mt][s], 1);
                rpart[mt][s] += __shfl_xor_sync(0xffffffffu, rpart[mt][s], 2);
            }
        }
        if (t == 0) {
            float* rs = rowsum + (size_t)blockIdx.z * SEQ + m0;
#pragma unroll
            for (int mt = 0; mt < MT; mt++) {
                atomicAdd(&rs[wm + mt * 16 + g],     rpart[mt][0]);
                atomicAdd(&rs[wm + mt * 16 + g + 8], rpart[mt][1]);
            }
        }
        return;
    }

#pragma unroll
    for (int mt = 0; mt < MT; mt++) {
        const int row = m0 + wm + mt * 16 + g;
#pragma unroll
        for (int nt = 0; nt < NTg; nt++) {
            const int col = n0 + wn + nt * 8 + 2 * t;
            float o0 = acc[mt][nt][0], o1 = acc[mt][nt][1];
            float o2 = acc[mt][nt][2], o3 = acc[mt][nt][3];
            if (bias) {
                const float b0 = bias[col], b1 = bias[col + 1];
                o0 += b0; o1 += b1; o2 += b0; o3 += b1;
            }
            if (scale != 1.f && col < scaleN) {
                o0 *= scale; o1 *= scale; o2 *= scale; o3 *= scale;
            }
            if (res) {
                float2 r0 = *(const float2*)&res[(size_t)row * ldcf + col];
                float2 r1 = *(const float2*)&res[(size_t)(row + 8) * ldcf + col];
                o0 += r0.x; o1 += r0.y; o2 += r1.x; o3 += r1.y;
            }
            if (relu) {
                o0 = fmaxf(o0, 0.f); o1 = fmaxf(o1, 0.f);
                o2 = fmaxf(o2, 0.f); o3 = fmaxf(o3, 0.f);
            }
            if (Ch) {
                *(__half2*)&Chp[(size_t)row * ldch + col] = __floats2half2_rn(o0, o1);
                *(__half2*)&Chp[(size_t)(row + 8) * ldch + col] = __floats2half2_rn(o2, o3);
            }
            if (Cf && MODE == 0) {
                *(float2*)&Cfp[(size_t)row * ldcf + col]       = make_float2(o0, o1);
                *(float2*)&Cfp[(size_t)(row + 8) * ldcf + col] = make_float2(o2, o3);
            }
        }
    }
}

// ================= layernorm (fp32 in; fp32 and/or fp16 out) ===============
__global__ __launch_bounds__(256) void layernorm_row(
    const float* __restrict__ in, float* __restrict__ outf,
    __half* __restrict__ outh,
    const float* __restrict__ g, const float* __restrict__ be)
{
    __shared__ float sm[8], sq[8];
    const size_t base = (size_t)blockIdx.x * DIM;
    const int tid = threadIdx.x;
    const int lane = tid & 31, wid = tid >> 5;

    float4 v = *(const float4*)&in[base + tid*4];
    float s  = v.x + v.y + v.z + v.w;
    float s2 = v.x*v.x + v.y*v.y + v.z*v.z + v.w*v.w;
#pragma unroll
    for (int o = 16; o; o >>= 1) {
        s  += __shfl_xor_sync(0xffffffffu, s,  o);
        s2 += __shfl_xor_sync(0xffffffffu, s2, o);
    }
    if (lane == 0) { sm[wid] = s; sq[wid] = s2; }
    __syncthreads();
    if (tid == 0) {
        float tt = 0.f, t2 = 0.f;
#pragma unroll
        for (int i = 0; i < 8; i++) { tt += sm[i]; t2 += sq[i]; }
        sm[0] = tt; sq[0] = t2;
    }
    __syncthreads();
    const float mean = sm[0] * (1.f / DIM);
    const float var  = sq[0] * (1.f / DIM) - mean * mean;
    const float r = rsqrtf(var + 1e-5f);

    float4 gg = *(const float4*)&g[tid*4];
    float4 bb = *(const float4*)&be[tid*4];
    float4 o4;
    o4.x = (v.x - mean) * r * gg.x + bb.x;
    o4.y = (v.y - mean) * r * gg.y + bb.y;
    o4.z = (v.z - mean) * r * gg.z + bb.z;
    o4.w = (v.w - mean) * r * gg.w + bb.w;
    if (outf) *(float4*)&outf[base + tid*4] = o4;
    if (outh) {
        __half2 lo = __floats2half2_rn(o4.x, o4.y);
        __half2 hi = __floats2half2_rn(o4.z, o4.w);
        uint2 u; u.x = *(uint32_t*)&lo; u.y = *(uint32_t*)&hi;
        *(uint2*)&outh[base + tid*4] = u;
    }
}

// ================= launcher ================================================
static const int SMEM_GEMM = 2 * (128 + 128) * HSTR * 2;   // 73728
static const int SMEM_PV   = 2 * (128 + 64) * HSTR * 2;    // 55296

extern "C" void kernel_launch(void* const* d_in, const int* in_sizes, int n_in,
                              void* d_out, int out_size)
{
    const float* x  = (const float*)d_in[0];
    const float* Wq = (const float*)d_in[1];
    const float* bq = (const float*)d_in[2];
    const float* Wk = (const float*)d_in[3];
    const float* bk = (const float*)d_in[4];
    const float* Wv = (const float*)d_in[5];
    const float* bv = (const float*)d_in[6];
    const float* Wf = (const float*)d_in[7];
    const float* bf = (const float*)d_in[8];
    const float* W1 = (const float*)d_in[9];
    const float* b1 = (const float*)d_in[10];
    const float* W2 = (const float*)d_in[11];
    const float* b2 = (const float*)d_in[12];
    const float* g1 = (const float*)d_in[13];
    const float* be1= (const float*)d_in[14];
    const float* g2 = (const float*)d_in[15];
    const float* be2= (const float*)d_in[16];

    float* out   = (float*)d_out;
    float* score = out + (size_t)MTOK * DIM;

    __half *pxh, *pwh, *pqkvh, *pvth, *peh, *pattnh, *ph1h, *pffnh;
    float *ph1f, *ptmpf, *pbias, *prsum, *prinv;
    cudaGetSymbolAddress((void**)&pxh,   g_xh);
    cudaGetSymbolAddress((void**)&pwh,   g_wh);
    cudaGetSymbolAddress((void**)&pqkvh, g_qkvh);
    cudaGetSymbolAddress((void**)&pvth,  g_vth);
    cudaGetSymbolAddress((void**)&peh,   g_eh);
    cudaGetSymbolAddress((void**)&pattnh,g_attnh);
    cudaGetSymbolAddress((void**)&ph1h,  g_h1h);
    cudaGetSymbolAddress((void**)&pffnh, g_ffnh);
    cudaGetSymbolAddress((void**)&ph1f,  g_h1f);
    cudaGetSymbolAddress((void**)&ptmpf, g_tmpf);
    cudaGetSymbolAddress((void**)&pbias, g_bqkv);
    cudaGetSymbolAddress((void**)&prsum, g_rowsum);
    cudaGetSymbolAddress((void**)&prinv, g_rowinv);

    __half* hWqkv = pwh;                    // 3M halves
    __half* hWf   = pwh + 3*1024*1024;
    __half* hW1   = pwh + 4*1024*1024;
    __half* hW2   = pwh + 6*1024*1024;

    cudaFuncSetAttribute(gemm_h<128,0>, cudaFuncAttributeMaxDynamicSharedMemorySize, SMEM_GEMM);
    cudaFuncSetAttribute(gemm_h<128,1>, cudaFuncAttributeMaxDynamicSharedMemorySize, SMEM_GEMM);
    cudaFuncSetAttribute(gemm_h<64,2>,  cudaFuncAttributeMaxDynamicSharedMemorySize, SMEM_PV);

    const float isq = 0.125f;  // 1/sqrt(64)

    // ---- prep: convert operands to fp16, bias concat, rowsum zero ----
    RC7 rc;
    rc.in[0] = x;  rc.out[0] = pxh;                 rc.n4[0] = MTOK*DIM/4;
    rc.in[1] = Wq; rc.out[1] = hWqkv;               rc.n4[1] = DIM*DIM/4;
    rc.in[2] = Wk; rc.out[2] = hWqkv + 1024*1024;   rc.n4[2] = DIM*DIM/4;
    rc.in[3] = Wv; rc.out[3] = hWqkv + 2*1024*1024; rc.n4[3] = DIM*DIM/4;
    rc.in[4] = Wf; rc.out[4] = hWf;                 rc.n4[4] = DIM*DIM/4;
    rc.in[5] = W1; rc.out[5] = hW1;                 rc.n4[5] = FFD*DIM/4;
    rc.in[6] = W2; rc.out[6] = hW2;                 rc.n4[6] = FFD*DIM/4;
    round_h<<<dim3(512, 7), 256>>>(rc);
    concat_bias<<<12, 256>>>(bq, bk, bv, pbias);
    zero_buf<<<NROW/256, 256>>>(prsum, NROW);

    // ---- fused QKV projection -> fp16 qkv ----
    gemm_h<128,0><<<dim3(QKVD/128, MTOK/128), 256, SMEM_GEMM>>>(
        pxh, hWqkv, pbias, nullptr, pqkvh, nullptr,
        DIM, DIM, DIM, QKVD, QKVD, isq, DIM, 0, nullptr, nullptr);

    // ---- V transpose for PV ----
    transpose_v<<<dim3(SEQ/32, DH/32, BSZ*NH), 256>>>(pqkvh, pvth);

    // ---- scores: e = exp(q.k^T) fp16 -> g_eh; rowsums accumulated ----
    gemm_h<128,1><<<dim3(SEQ/128, SEQ/128, BSZ*NH), 256, SMEM_GEMM>>>(
        pqkvh, pqkvh + DIM, nullptr, nullptr, peh, nullptr,
        DH, QKVD, QKVD, SEQ, SEQ, 1.f, 0, 0, prsum, nullptr);
    recip_buf<<<NROW/256, 256>>>(prsum, prinv, NROW);

    // ---- PV: attn fp16; fp32 P -> d_out score region ----
    gemm_h<64,2><<<dim3(1, SEQ/128, BSZ*NH), 256, SMEM_PV>>>(
        peh, pvth, nullptr, nullptr, pattnh, score,
        SEQ, SEQ, SEQ, DIM, SEQ, 1.f, 0, 0, nullptr, prinv);

    // ---- output projection + residual (x fp32), LN1 ----
    gemm_h<128,0><<<dim3(DIM/128, MTOK/128), 256, SMEM_GEMM>>>(
        pattnh, hWf, bf, x, nullptr, ph1f,
        DIM, DIM, DIM, DIM, DIM, 1.f, 0, 0, nullptr, nullptr);
    layernorm_row<<<MTOK, 256>>>(ph1f, ph1f, ph1h, g1, be1);

    // ---- FFN ----
    gemm_h<128,0><<<dim3(FFD/128, MTOK/128), 256, SMEM_GEMM>>>(
        ph1h, hW1, b1, nullptr, pffnh, nullptr,
        DIM, DIM, DIM, FFD, FFD, 1.f, 0, 1, nullptr, nullptr);
    gemm_h<128,0><<<dim3(DIM/128, MTOK/128), 256, SMEM_GEMM>>>(
        pffnh, hW2, b2, ph1f, nullptr, ptmpf,
        FFD, FFD, FFD, DIM, DIM, 1.f, 0, 0, nullptr, nullptr);
    layernorm_row<<<MTOK, 256>>>(ptmpf, out, nullptr, g2, be2);
}